// round 2
// baseline (speedup 1.0000x reference)
#include <cuda_runtime.h>
#include <cstddef>
#include <math.h>

#define N_NODES 100000
#define N_EDGES 1600000
#define N_POS   200000
#define N_NEG   200000
#define IN_C    128
#define HID_C   128
#define OUT_C   64
#define BN_EPS  1e-5f

// ---------------- scratch (static device globals; no allocation) ----------------
__device__ float g_yl[N_NODES * HID_C];   // transformed-for-aggregation features (also reused as P)
__device__ float g_yr[N_NODES * HID_C];   // root-transformed features (also reused as Q)
__device__ float g_hA[N_NODES * HID_C];   // hidden after layer 1
__device__ float g_hB[N_NODES * HID_C];   // hidden after layer 2
__device__ int   g_count[N_NODES];        // in-degree per node
__device__ int   g_off[N_NODES];          // CSR row offsets (exclusive scan of count)
__device__ int   g_cur[N_NODES];          // fill cursors
__device__ int   g_part[256];             // scan partials
__device__ int   g_srcs[N_EDGES];         // CSR: source node per incoming edge, grouped by dst

// ---------------- CSR build ----------------
__global__ void k_count(const int* __restrict__ dst) {
    int i = blockIdx.x * blockDim.x + threadIdx.x;
    if (i < N_EDGES) atomicAdd(&g_count[dst[i]], 1);
}

__global__ void k_scan1() {
    __shared__ int sm[1024];
    int i = blockIdx.x * 1024 + threadIdx.x;
    int v = (i < N_NODES) ? g_count[i] : 0;
    sm[threadIdx.x] = v;
    __syncthreads();
    #pragma unroll
    for (int s = 1; s < 1024; s <<= 1) {
        int t = (threadIdx.x >= s) ? sm[threadIdx.x - s] : 0;
        __syncthreads();
        sm[threadIdx.x] += t;
        __syncthreads();
    }
    if (i < N_NODES) g_off[i] = sm[threadIdx.x] - v;   // exclusive within block
    if (threadIdx.x == 1023) g_part[blockIdx.x] = sm[1023];
}

__global__ void k_scan2(int nb) {
    if (threadIdx.x == 0 && blockIdx.x == 0) {
        int run = 0;
        for (int j = 0; j < nb; j++) { int t = g_part[j]; g_part[j] = run; run += t; }
    }
}

__global__ void k_scan3() {
    int i = blockIdx.x * 1024 + threadIdx.x;
    if (i < N_NODES) {
        int o = g_off[i] + g_part[blockIdx.x];
        g_off[i] = o;
        g_cur[i] = o;
    }
}

__global__ void k_fill(const int* __restrict__ src, const int* __restrict__ dst) {
    int i = blockIdx.x * blockDim.x + threadIdx.x;
    if (i < N_EDGES) {
        int d = dst[i];
        int p = atomicAdd(&g_cur[d], 1);
        g_srcs[p] = src[i];
    }
}

// ---------------- SGEMM: C[N,M] = A[N,K] @ W[K,M] (+bias) ----------------
// BM=128, BN=64, BK=32, 256 threads, 8x4 microtile per thread.
__global__ __launch_bounds__(256) void k_sgemm(
    const float* __restrict__ A, const float* __restrict__ W,
    const float* __restrict__ bias, float* __restrict__ C,
    int N, int K, int M)
{
    __shared__ float As[128][33];   // padded: conflict-free column reads
    __shared__ float Ws[32][64];

    const int tx = threadIdx.x & 15;        // 0..15 -> col group
    const int ty = threadIdx.x >> 4;        // 0..15 -> row group
    const int row0 = blockIdx.y * 128;
    const int col0 = blockIdx.x * 64;

    float acc[8][4];
    #pragma unroll
    for (int i = 0; i < 8; i++)
        #pragma unroll
        for (int j = 0; j < 4; j++) acc[i][j] = 0.0f;

    for (int k0 = 0; k0 < K; k0 += 32) {
        // A tile: 128x32 = 1024 float4; 4 per thread
        #pragma unroll
        for (int l = 0; l < 4; l++) {
            int fidx = threadIdx.x + l * 256;
            int r = fidx >> 3, c4 = fidx & 7;
            int grow = row0 + r;
            float4 v = make_float4(0.f, 0.f, 0.f, 0.f);
            if (grow < N) v = *reinterpret_cast<const float4*>(&A[(size_t)grow * K + k0 + c4 * 4]);
            As[r][c4 * 4 + 0] = v.x;
            As[r][c4 * 4 + 1] = v.y;
            As[r][c4 * 4 + 2] = v.z;
            As[r][c4 * 4 + 3] = v.w;
        }
        // W tile: 32x64 = 512 float4; 2 per thread
        #pragma unroll
        for (int l = 0; l < 2; l++) {
            int fidx = threadIdx.x + l * 256;
            int r = fidx >> 4, c4 = fidx & 15;
            float4 v = *reinterpret_cast<const float4*>(&W[(size_t)(k0 + r) * M + col0 + c4 * 4]);
            *reinterpret_cast<float4*>(&Ws[r][c4 * 4]) = v;
        }
        __syncthreads();

        #pragma unroll
        for (int kk = 0; kk < 32; kk++) {
            float4 wv = *reinterpret_cast<const float4*>(&Ws[kk][tx * 4]);
            #pragma unroll
            for (int i = 0; i < 8; i++) {
                float a = As[ty * 8 + i][kk];
                acc[i][0] += a * wv.x;
                acc[i][1] += a * wv.y;
                acc[i][2] += a * wv.z;
                acc[i][3] += a * wv.w;
            }
        }
        __syncthreads();
    }

    float4 bb = make_float4(0.f, 0.f, 0.f, 0.f);
    if (bias) bb = *reinterpret_cast<const float4*>(&bias[col0 + tx * 4]);

    #pragma unroll
    for (int i = 0; i < 8; i++) {
        int grow = row0 + ty * 8 + i;
        if (grow < N) {
            float4 o = make_float4(acc[i][0] + bb.x, acc[i][1] + bb.y,
                                   acc[i][2] + bb.z, acc[i][3] + bb.w);
            *reinterpret_cast<float4*>(&C[(size_t)grow * M + col0 + tx * 4]) = o;
        }
    }
}

// ---------------- fused aggregation + combine ----------------
// per thread: one (node, float4-channel-group). out = mean_agg(yl) + bl + yr, then
// optionally BN(eval) + ReLU + residual(h_in).
template<int C, bool FULL>
__global__ void k_agg(const float* __restrict__ bl,
                      const float* __restrict__ gam, const float* __restrict__ bet,
                      const float* __restrict__ h_in, float* __restrict__ h_out,
                      const float* __restrict__ yl, const float* __restrict__ yr)
{
    constexpr int C4 = C / 4;
    int idx = blockIdx.x * blockDim.x + threadIdx.x;
    if (idx >= N_NODES * C4) return;
    int n  = idx / C4;
    int c4 = idx % C4;
    int beg = g_off[n];
    int cnt = g_count[n];

    float4 acc = make_float4(0.f, 0.f, 0.f, 0.f);
    for (int e = 0; e < cnt; e++) {
        int s = g_srcs[beg + e];
        float4 v = *reinterpret_cast<const float4*>(&yl[(size_t)s * C + c4 * 4]);
        acc.x += v.x; acc.y += v.y; acc.z += v.z; acc.w += v.w;
    }
    float inv = 1.0f / fmaxf((float)cnt, 1.0f);

    int off = n * C + c4 * 4;
    float4 r = *reinterpret_cast<const float4*>(&yr[off]);
    float4 b = *reinterpret_cast<const float4*>(&bl[c4 * 4]);
    float4 o;
    o.x = acc.x * inv + b.x + r.x;
    o.y = acc.y * inv + b.y + r.y;
    o.z = acc.z * inv + b.z + r.z;
    o.w = acc.w * inv + b.w + r.w;

    if constexpr (FULL) {
        const float s = rsqrtf(1.0f + BN_EPS);
        float4 g  = *reinterpret_cast<const float4*>(&gam[c4 * 4]);
        float4 bt = *reinterpret_cast<const float4*>(&bet[c4 * 4]);
        float4 h  = *reinterpret_cast<const float4*>(&h_in[off]);
        o.x = fmaxf(o.x * (g.x * s) + bt.x, 0.f) + h.x;
        o.y = fmaxf(o.y * (g.y * s) + bt.y, 0.f) + h.y;
        o.z = fmaxf(o.z * (g.z * s) + bt.z, 0.f) + h.z;
        o.w = fmaxf(o.w * (g.w * s) + bt.w, 0.f) + h.w;
    }
    *reinterpret_cast<float4*>(&h_out[off]) = o;
}

// ---------------- edge decode: sigmoid(relu(P[s]+Q[d]) . We2 + be2) ----------------
__global__ void k_decode(const int* __restrict__ sidx, const int* __restrict__ didx, int E,
                         const float* __restrict__ We2, const float* __restrict__ be2,
                         float* __restrict__ out,
                         const float* __restrict__ P, const float* __restrict__ Q)
{
    int warp = (blockIdx.x * blockDim.x + threadIdx.x) >> 5;
    int lane = threadIdx.x & 31;
    if (warp >= E) return;
    int s = sidx[warp], d = didx[warp];
    float sum = 0.f;
    #pragma unroll
    for (int k = 0; k < 4; k++) {
        int c = lane + k * 32;
        float v = P[(size_t)s * HID_C + c] + Q[(size_t)d * HID_C + c];
        v = fmaxf(v, 0.f);
        sum += v * We2[c];
    }
    #pragma unroll
    for (int o = 16; o; o >>= 1) sum += __shfl_xor_sync(0xFFFFFFFFu, sum, o);
    if (lane == 0) out[warp] = 1.0f / (1.0f + expf(-(sum + be2[0])));
}

// ---------------- host launcher ----------------
extern "C" void kernel_launch(void* const* d_in, const int* in_sizes, int n_in,
                              void* d_out, int out_size)
{
    const float* x    = (const float*)d_in[0];
    const int*   ei   = (const int*)d_in[1];     // [2, N_EDGES]: src row 0, dst row 1
    const int*   pos  = (const int*)d_in[2];     // [2, N_POS]
    const int*   neg  = (const int*)d_in[3];     // [2, N_NEG]
    const float* Wl1  = (const float*)d_in[4];
    const float* bl1  = (const float*)d_in[5];
    const float* Wr1  = (const float*)d_in[6];
    const float* g1   = (const float*)d_in[7];
    const float* b1   = (const float*)d_in[8];
    const float* Wl2  = (const float*)d_in[9];
    const float* bl2  = (const float*)d_in[10];
    const float* Wr2  = (const float*)d_in[11];
    const float* g2   = (const float*)d_in[12];
    const float* b2   = (const float*)d_in[13];
    const float* Wl3  = (const float*)d_in[14];
    const float* bl3  = (const float*)d_in[15];
    const float* Wr3  = (const float*)d_in[16];
    const float* We1  = (const float*)d_in[17];  // [128, 128]
    const float* be1  = (const float*)d_in[18];
    const float* We2  = (const float*)d_in[19];  // [128, 1]
    const float* be2  = (const float*)d_in[20];

    float* out    = (float*)d_out;
    float* z      = out;                          // [N_NODES, 64]
    float* outpos = out + (size_t)N_NODES * OUT_C;
    float* outneg = outpos + N_POS;

    float *yl, *yr, *hA, *hB;
    int* cnt;
    cudaGetSymbolAddress((void**)&yl, g_yl);
    cudaGetSymbolAddress((void**)&yr, g_yr);
    cudaGetSymbolAddress((void**)&hA, g_hA);
    cudaGetSymbolAddress((void**)&hB, g_hB);
    cudaGetSymbolAddress((void**)&cnt, g_count);

    const int EB = (N_EDGES + 255) / 256;
    const int SCAN_NB = (N_NODES + 1023) / 1024;   // 98

    // ---- CSR build (once per launch; amortized over 3 layers) ----
    cudaMemsetAsync(cnt, 0, N_NODES * sizeof(int), 0);
    k_count<<<EB, 256>>>(ei + N_EDGES);
    k_scan1<<<SCAN_NB, 1024>>>();
    k_scan2<<<1, 32>>>(SCAN_NB);
    k_scan3<<<SCAN_NB, 1024>>>();
    k_fill<<<EB, 256>>>(ei, ei + N_EDGES);

    dim3 g128(2, (N_NODES + 127) / 128);   // M=128
    dim3 g64 (1, (N_NODES + 127) / 128);   // M=64
    const int AGG128_B = (N_NODES * (HID_C / 4) + 255) / 256;
    const int AGG64_B  = (N_NODES * (OUT_C / 4) + 255) / 256;

    // ---- layer 1 ----
    k_sgemm<<<g128, 256>>>(x, Wl1, nullptr, yl, N_NODES, IN_C, HID_C);
    k_sgemm<<<g128, 256>>>(x, Wr1, nullptr, yr, N_NODES, IN_C, HID_C);
    k_agg<HID_C, true><<<AGG128_B, 256>>>(bl1, g1, b1, x, hA, yl, yr);

    // ---- layer 2 ----
    k_sgemm<<<g128, 256>>>(hA, Wl2, nullptr, yl, N_NODES, HID_C, HID_C);
    k_sgemm<<<g128, 256>>>(hA, Wr2, nullptr, yr, N_NODES, HID_C, HID_C);
    k_agg<HID_C, true><<<AGG128_B, 256>>>(bl2, g2, b2, hA, hB, yl, yr);

    // ---- layer 3 (no BN/ReLU/residual), writes z directly into d_out ----
    k_sgemm<<<g64, 256>>>(hB, Wl3, nullptr, yl, N_NODES, HID_C, OUT_C);
    k_sgemm<<<g64, 256>>>(hB, Wr3, nullptr, yr, N_NODES, HID_C, OUT_C);
    k_agg<OUT_C, false><<<AGG64_B, 256>>>(bl3, nullptr, nullptr, nullptr, z, yl, yr);

    // ---- decode prep: P = z @ We1[0:64,:] + be1 ; Q = z @ We1[64:128,:] ----
    k_sgemm<<<g128, 256>>>(z, We1, be1, yl, N_NODES, OUT_C, HID_C);
    k_sgemm<<<g128, 256>>>(z, We1 + (size_t)OUT_C * HID_C, nullptr, yr, N_NODES, OUT_C, HID_C);

    // ---- decode ----
    k_decode<<<(N_POS * 32 + 127) / 128, 128>>>(pos, pos + N_POS, N_POS, We2, be2, outpos, yl, yr);
    k_decode<<<(N_NEG * 32 + 127) / 128, 128>>>(neg, neg + N_NEG, N_NEG, We2, be2, outneg, yl, yr);
}

// round 4
// speedup vs baseline: 1.6529x; 1.6529x over previous
#include <cuda_runtime.h>
#include <cstdint>
#include <cstddef>
#include <math.h>

#define N_NODES 100000
#define N_EDGES 1600000
#define N_POS   200000
#define N_NEG   200000
#define IN_C    128
#define HID_C   128
#define OUT_C   64
#define BN_EPS  1e-5f

// ---------------- scratch (static device globals; no allocation) ----------------
__device__ float g_y[N_NODES * 256];      // fused GEMM output [yl | yr] per node
__device__ float g_hA[N_NODES * HID_C];   // hidden after layer 1
__device__ float g_hB[N_NODES * HID_C];   // hidden after layer 2
__device__ float g_wt[256 * 128];         // transposed+fused weights for current GEMM
__device__ int   g_count[N_NODES];
__device__ int   g_off[N_NODES];
__device__ int   g_cur[N_NODES];
__device__ int   g_part[256];
__device__ int   g_srcs[N_EDGES];

// tf32 round-to-nearest (keeps accuracy vs implicit truncation)
__device__ __forceinline__ uint32_t f2tf32(float f) {
    uint32_t r;
    asm("cvt.rna.tf32.f32 %0, %1;" : "=r"(r) : "f"(f));
    return r;
}

// ---------------- CSR build ----------------
__global__ void k_count(const int* __restrict__ dst) {
    int i = blockIdx.x * blockDim.x + threadIdx.x;
    if (i < N_EDGES) atomicAdd(&g_count[dst[i]], 1);
}
__global__ void k_scan1() {
    __shared__ int sm[1024];
    int i = blockIdx.x * 1024 + threadIdx.x;
    int v = (i < N_NODES) ? g_count[i] : 0;
    sm[threadIdx.x] = v;
    __syncthreads();
    #pragma unroll
    for (int s = 1; s < 1024; s <<= 1) {
        int t = (threadIdx.x >= s) ? sm[threadIdx.x - s] : 0;
        __syncthreads();
        sm[threadIdx.x] += t;
        __syncthreads();
    }
    if (i < N_NODES) g_off[i] = sm[threadIdx.x] - v;
    if (threadIdx.x == 1023) g_part[blockIdx.x] = sm[1023];
}
__global__ void k_scan2(int nb) {
    if (threadIdx.x == 0 && blockIdx.x == 0) {
        int run = 0;
        for (int j = 0; j < nb; j++) { int t = g_part[j]; g_part[j] = run; run += t; }
    }
}
__global__ void k_scan3() {
    int i = blockIdx.x * 1024 + threadIdx.x;
    if (i < N_NODES) {
        int o = g_off[i] + g_part[blockIdx.x];
        g_off[i] = o;
        g_cur[i] = o;
    }
}
__global__ void k_fill(const int* __restrict__ src, const int* __restrict__ dst) {
    int i = blockIdx.x * blockDim.x + threadIdx.x;
    if (i < N_EDGES) {
        int d = dst[i];
        int p = atomicAdd(&g_cur[d], 1);
        g_srcs[p] = src[i];
    }
}

// ---------------- weight prep: Wt[2*Mh, K]; rows 0:Mh = s1^T, Mh: = s2^T ----------------
__global__ void k_prep(const float* __restrict__ s1, const float* __restrict__ s2,
                       float* __restrict__ wt, int K, int Mh) {
    int i = blockIdx.x * 256 + threadIdx.x;
    int tot = 2 * Mh * K;
    if (i >= tot) return;
    int m = i / K, k = i % K;
    wt[i] = (m < Mh) ? s1[(size_t)k * Mh + m] : s2[(size_t)k * Mh + (m - Mh)];
}

// ---------------- tf32 mma.sync GEMM: C[Nrows, NOUT] = A[Nrows, K] @ Wt[NOUT, K]^T ----
// CTA: 128 rows x 128 cols (grid.y = NOUT/128 panels). 8 warps (4 row-groups x 2
// col-groups), each warp 32x64 via m16n8k8 fragments. BK=32 smem chunks, pad->36.
template<int K>
__global__ __launch_bounds__(256, 2) void k_mma(const float* __restrict__ A,
                                                const float* __restrict__ Wt,
                                                float* __restrict__ C,
                                                int Nrows, int NOUT) {
    __shared__ float As[128][36];
    __shared__ float Bs[128][36];

    const int tid  = threadIdx.x;
    const int lane = tid & 31, wid = tid >> 5;
    const int gid  = lane >> 2, tg = lane & 3;
    const int mrow = (wid & 3) * 32;
    const int ncol = (wid >> 2) * 64;
    const int row0 = blockIdx.x * 128;
    const int col0 = blockIdx.y * 128;

    float c[2][8][4];
    #pragma unroll
    for (int mt = 0; mt < 2; mt++)
        #pragma unroll
        for (int nt = 0; nt < 8; nt++)
            #pragma unroll
            for (int j = 0; j < 4; j++) c[mt][nt][j] = 0.f;

    for (int k0 = 0; k0 < K; k0 += 32) {
        // stage A chunk: 128 rows x 32 k (1024 float4, 4 per thread)
        #pragma unroll
        for (int l = 0; l < 4; l++) {
            int f = tid + l * 256;
            int r = f >> 3, c4 = f & 7;
            int grow = row0 + r;
            float4 v = make_float4(0.f, 0.f, 0.f, 0.f);
            if (grow < Nrows) v = *(const float4*)(A + (size_t)grow * K + k0 + c4 * 4);
            float4 t;
            t.x = __uint_as_float(f2tf32(v.x));
            t.y = __uint_as_float(f2tf32(v.y));
            t.z = __uint_as_float(f2tf32(v.z));
            t.w = __uint_as_float(f2tf32(v.w));
            *(float4*)&As[r][c4 * 4] = t;
        }
        // stage B chunk: 128 out-cols (this panel) x 32 k
        #pragma unroll
        for (int l = 0; l < 4; l++) {
            int f = tid + l * 256;
            int r = f >> 3, c4 = f & 7;
            float4 v = *(const float4*)(Wt + (size_t)(col0 + r) * K + k0 + c4 * 4);
            float4 t;
            t.x = __uint_as_float(f2tf32(v.x));
            t.y = __uint_as_float(f2tf32(v.y));
            t.z = __uint_as_float(f2tf32(v.z));
            t.w = __uint_as_float(f2tf32(v.w));
            *(float4*)&Bs[r][c4 * 4] = t;
        }
        __syncthreads();

        #pragma unroll
        for (int ks = 0; ks < 4; ks++) {
            uint32_t a[2][4];
            #pragma unroll
            for (int mt = 0; mt < 2; mt++) {
                int r = mrow + mt * 16 + gid;
                a[mt][0] = __float_as_uint(As[r][ks * 8 + tg]);
                a[mt][1] = __float_as_uint(As[r + 8][ks * 8 + tg]);
                a[mt][2] = __float_as_uint(As[r][ks * 8 + tg + 4]);
                a[mt][3] = __float_as_uint(As[r + 8][ks * 8 + tg + 4]);
            }
            uint32_t b[8][2];
            #pragma unroll
            for (int nt = 0; nt < 8; nt++) {
                int rn = ncol + nt * 8 + gid;
                b[nt][0] = __float_as_uint(Bs[rn][ks * 8 + tg]);
                b[nt][1] = __float_as_uint(Bs[rn][ks * 8 + tg + 4]);
            }
            #pragma unroll
            for (int mt = 0; mt < 2; mt++)
                #pragma unroll
                for (int nt = 0; nt < 8; nt++)
                    asm volatile(
                        "mma.sync.aligned.m16n8k8.row.col.f32.tf32.tf32.f32 "
                        "{%0,%1,%2,%3}, {%4,%5,%6,%7}, {%8,%9}, {%0,%1,%2,%3};"
                        : "+f"(c[mt][nt][0]), "+f"(c[mt][nt][1]),
                          "+f"(c[mt][nt][2]), "+f"(c[mt][nt][3])
                        : "r"(a[mt][0]), "r"(a[mt][1]), "r"(a[mt][2]), "r"(a[mt][3]),
                          "r"(b[nt][0]), "r"(b[nt][1]));
        }
        __syncthreads();
    }

    // epilogue: c0,c1 -> (row, col..col+1); c2,c3 -> (row+8, col..col+1)
    #pragma unroll
    for (int mt = 0; mt < 2; mt++) {
        int r0 = row0 + mrow + mt * 16 + gid;
        int r1 = r0 + 8;
        #pragma unroll
        for (int nt = 0; nt < 8; nt++) {
            int col = col0 + ncol + nt * 8 + 2 * tg;
            if (r0 < Nrows)
                *(float2*)(C + (size_t)r0 * NOUT + col) = make_float2(c[mt][nt][0], c[mt][nt][1]);
            if (r1 < Nrows)
                *(float2*)(C + (size_t)r1 * NOUT + col) = make_float2(c[mt][nt][2], c[mt][nt][3]);
        }
    }
}

// ---------------- fused aggregation + combine (warp per node) ----------------
// y layout: [n][STRIDE]; cols 0:C = A@Wl, cols C:2C = A@Wr
template<int C, int STRIDE, bool FULL>
__global__ __launch_bounds__(256) void k_aggw(const float* __restrict__ bl,
                                              const float* __restrict__ gam,
                                              const float* __restrict__ bet,
                                              const float* __restrict__ h_in,
                                              float* __restrict__ h_out,
                                              const float* __restrict__ y) {
    constexpr int V = C / 32;   // floats per lane (4 or 2)
    int warp = (blockIdx.x * 256 + threadIdx.x) >> 5;
    int lane = threadIdx.x & 31;
    if (warp >= N_NODES) return;
    int n = warp;
    int beg = g_off[n], cnt = g_count[n];

    float acc[V];
    #pragma unroll
    for (int j = 0; j < V; j++) acc[j] = 0.f;

    for (int e0 = 0; e0 < cnt; e0 += 32) {
        int m = min(32, cnt - e0);
        int myidx = (lane < m) ? g_srcs[beg + e0 + lane] : 0;
        for (int i = 0; i < m; i++) {
            int s = __shfl_sync(0xFFFFFFFFu, myidx, i);
            const float* rp = y + (size_t)s * STRIDE + lane * V;
            if (V == 4) {
                float4 v = *(const float4*)rp;
                acc[0] += v.x; acc[1] += v.y; acc[2] += v.z; acc[3] += v.w;
            } else {
                float2 v = *(const float2*)rp;
                acc[0] += v.x; acc[1] += v.y;
            }
        }
    }
    float inv = 1.0f / fmaxf((float)cnt, 1.0f);

    float o[V];
    {
        const float* rr = y + (size_t)n * STRIDE + C + lane * V;
        #pragma unroll
        for (int j = 0; j < V; j++)
            o[j] = acc[j] * inv + bl[lane * V + j] + rr[j];
    }
    if (FULL) {
        const float s = rsqrtf(1.0f + BN_EPS);
        const float* hp = h_in + (size_t)n * C + lane * V;
        #pragma unroll
        for (int j = 0; j < V; j++) {
            int ch = lane * V + j;
            o[j] = fmaxf(o[j] * (gam[ch] * s) + bet[ch], 0.f) + hp[j];
        }
    }
    float* op = h_out + (size_t)n * C + lane * V;
    if (V == 4) *(float4*)op = make_float4(o[0], o[1], o[2], o[3 < V ? 3 : V - 1]);
    else        *(float2*)op = make_float2(o[0], o[1]);
}

// ---------------- edge decode: sigmoid(relu(P[s]+Q[d]+be1) . We2 + be2) --------
__global__ void k_decode(const int* __restrict__ sidx, const int* __restrict__ didx, int E,
                         const float* __restrict__ be1,
                         const float* __restrict__ We2, const float* __restrict__ be2,
                         float* __restrict__ out, const float* __restrict__ y) {
    int warp = (blockIdx.x * blockDim.x + threadIdx.x) >> 5;
    int lane = threadIdx.x & 31;
    if (warp >= E) return;
    int s = sidx[warp], d = didx[warp];
    float sum = 0.f;
    #pragma unroll
    for (int k = 0; k < 4; k++) {
        int c = lane + k * 32;
        float v = y[(size_t)s * 256 + c] + y[(size_t)d * 256 + 128 + c] + be1[c];
        v = fmaxf(v, 0.f);
        sum += v * We2[c];
    }
    #pragma unroll
    for (int o = 16; o; o >>= 1) sum += __shfl_xor_sync(0xFFFFFFFFu, sum, o);
    if (lane == 0) out[warp] = 1.0f / (1.0f + expf(-(sum + be2[0])));
}

// ---------------- host launcher ----------------
extern "C" void kernel_launch(void* const* d_in, const int* in_sizes, int n_in,
                              void* d_out, int out_size) {
    const float* x   = (const float*)d_in[0];
    const int*   ei  = (const int*)d_in[1];
    const int*   pos = (const int*)d_in[2];
    const int*   neg = (const int*)d_in[3];
    const float* Wl1 = (const float*)d_in[4];
    const float* bl1 = (const float*)d_in[5];
    const float* Wr1 = (const float*)d_in[6];
    const float* g1  = (const float*)d_in[7];
    const float* b1  = (const float*)d_in[8];
    const float* Wl2 = (const float*)d_in[9];
    const float* bl2 = (const float*)d_in[10];
    const float* Wr2 = (const float*)d_in[11];
    const float* g2  = (const float*)d_in[12];
    const float* b2  = (const float*)d_in[13];
    const float* Wl3 = (const float*)d_in[14];
    const float* bl3 = (const float*)d_in[15];
    const float* Wr3 = (const float*)d_in[16];
    const float* We1 = (const float*)d_in[17];
    const float* be1 = (const float*)d_in[18];
    const float* We2 = (const float*)d_in[19];
    const float* be2 = (const float*)d_in[20];

    float* out    = (float*)d_out;
    float* z      = out;
    float* outpos = out + (size_t)N_NODES * OUT_C;
    float* outneg = outpos + N_POS;

    float *y, *hA, *hB, *wt;
    int* cnt;
    cudaGetSymbolAddress((void**)&y, g_y);
    cudaGetSymbolAddress((void**)&hA, g_hA);
    cudaGetSymbolAddress((void**)&hB, g_hB);
    cudaGetSymbolAddress((void**)&wt, g_wt);
    cudaGetSymbolAddress((void**)&cnt, g_count);

    const int EB = (N_EDGES + 255) / 256;
    const int SCAN_NB = (N_NODES + 1023) / 1024;
    const int GT = (N_NODES + 127) / 128;           // 782 row tiles
    const int AGGB = (N_NODES * 32 + 255) / 256;    // warp per node

    // ---- CSR build ----
    cudaMemsetAsync(cnt, 0, N_NODES * sizeof(int), 0);
    k_count<<<EB, 256>>>(ei + N_EDGES);
    k_scan1<<<SCAN_NB, 1024>>>();
    k_scan2<<<1, 32>>>(SCAN_NB);
    k_scan3<<<SCAN_NB, 1024>>>();
    k_fill<<<EB, 256>>>(ei, ei + N_EDGES);

    dim3 gA(GT, 2);   // NOUT=256 (fused Wl|Wr, C=128)
    dim3 gB(GT, 1);   // NOUT=128 (fused Wl3|Wr3, C=64)

    // ---- layer 1 ----
    k_prep<<<(2 * 128 * 128 + 255) / 256, 256>>>(Wl1, Wr1, wt, 128, 128);
    k_mma<128><<<gA, 256>>>(x, wt, y, N_NODES, 256);
    k_aggw<128, 256, true><<<AGGB, 256>>>(bl1, g1, b1, x, hA, y);

    // ---- layer 2 ----
    k_prep<<<(2 * 128 * 128 + 255) / 256, 256>>>(Wl2, Wr2, wt, 128, 128);
    k_mma<128><<<gA, 256>>>(hA, wt, y, N_NODES, 256);
    k_aggw<128, 256, true><<<AGGB, 256>>>(bl2, g2, b2, hA, hB, y);

    // ---- layer 3 (no BN/ReLU/residual) ----
    k_prep<<<(2 * 64 * 128 + 255) / 256, 256>>>(Wl3, Wr3, wt, 128, 64);
    k_mma<128><<<gB, 256>>>(hB, wt, y, N_NODES, 128);
    k_aggw<64, 128, false><<<AGGB, 256>>>(bl3, nullptr, nullptr, nullptr, z, y);

    // ---- decode prep: y[:,0:128]=P=z@We1_top, y[:,128:256]=Q=z@We1_bot ----
    k_prep<<<(2 * 128 * 64 + 255) / 256, 256>>>(We1, We1 + 64 * 128, wt, 64, 128);
    k_mma<64><<<gA, 256>>>(z, wt, y, N_NODES, 256);

    // ---- decode ----
    k_decode<<<(N_POS * 32 + 127) / 128, 128>>>(pos, pos + N_POS, N_POS, be1, We2, be2, outpos, y);
    k_decode<<<(N_NEG * 32 + 127) / 128, 128>>>(neg, neg + N_NEG, N_NEG, be1, We2, be2, outneg, y);
}